// round 5
// baseline (speedup 1.0000x reference)
#include <cuda_runtime.h>
#include <math.h>

#define NT_MAX 64
#define L_MAX  4096

__device__ float g_P[NT_MAX * NT_MAX];   // time softmax table P[r][t]
__device__ float g_bias[L_MAX];          // id_emb @ socail_uid_emb

// ---------------------------------------------------------------------------
// Kernel 1: build the 48x48 time-attention table.
// softmax_l(T[r, his_t[l]]) factorizes through the histogram of his_t:
//   denom_r = sum_t cnt[t] * exp(T[r][t] - max_r)
//   P[r][t] = exp(T[r][t] - max_r) / denom_r
// ---------------------------------------------------------------------------
__global__ void time_table_kernel(const int* __restrict__ his_t, int L,
                                  const float* __restrict__ T, int NT) {
    __shared__ int scnt[NT_MAX];
    int tid = threadIdx.x;
    if (tid < NT_MAX) scnt[tid] = 0;
    __syncthreads();
    for (int l = tid; l < L; l += blockDim.x)
        atomicAdd(&scnt[his_t[l]], 1);
    __syncthreads();
    if (tid < NT) {
        int r = tid;
        float mx = -INFINITY;
        for (int t = 0; t < NT; ++t)
            if (scnt[t] > 0) mx = fmaxf(mx, T[r * NT + t]);
        float denom = 0.f;
        for (int t = 0; t < NT; ++t)
            if (scnt[t] > 0) denom += (float)scnt[t] * __expf(T[r * NT + t] - mx);
        float inv = 1.0f / denom;
        for (int t = 0; t < NT; ++t)
            g_P[r * NT_MAX + t] = __expf(T[r * NT + t] - mx) * inv;
    }
}

// ---------------------------------------------------------------------------
// Kernel 2: bias[l] = id_emb[l] . socail_uid_emb   (one warp per row)
// ---------------------------------------------------------------------------
__global__ void bias_kernel(const float* __restrict__ id_emb,
                            const float* __restrict__ soc,
                            int L, int D) {
    int warp = (blockIdx.x * blockDim.x + threadIdx.x) >> 5;
    int lane = threadIdx.x & 31;
    if (warp >= L) return;
    const float* row = id_emb + (size_t)warp * D;
    float s = 0.f;
    for (int k = lane; k < D; k += 32) s += row[k] * soc[k];
    #pragma unroll
    for (int o = 16; o; o >>= 1) s += __shfl_xor_sync(0xffffffffu, s, o);
    if (lane == 0) g_bias[warp] = s;
}

// ---------------------------------------------------------------------------
// block-wide reduce (max or sum), 256 threads
// ---------------------------------------------------------------------------
__device__ __forceinline__ float block_reduce(float v, bool is_max, float* red) {
    int lane = threadIdx.x & 31, wid = threadIdx.x >> 5;
    #pragma unroll
    for (int o = 16; o; o >>= 1) {
        float u = __shfl_xor_sync(0xffffffffu, v, o);
        v = is_max ? fmaxf(v, u) : (v + u);
    }
    __syncthreads();                 // protect red[] against previous use
    if (lane == 0) red[wid] = v;
    __syncthreads();
    int nw = blockDim.x >> 5;
    if (wid == 0) {
        float x = (lane < nw) ? red[lane] : (is_max ? -INFINITY : 0.f);
        #pragma unroll
        for (int o = 16; o; o >>= 1) {
            float u = __shfl_xor_sync(0xffffffffu, x, o);
            x = is_max ? fmaxf(x, u) : (x + u);
        }
        if (lane == 0) red[0] = x;
    }
    __syncthreads();
    return red[0];
}

// ---------------------------------------------------------------------------
// Kernel 3: per-row s -> attn_loc (gather + softmax in smem) and
//           attn_time (pure table gather through g_P).
// ---------------------------------------------------------------------------
__global__ void row_loc_time_kernel(const int* __restrict__ his,
                                    const int* __restrict__ cur,
                                    const int* __restrict__ his_t,
                                    const int* __restrict__ cur_t,
                                    const float* __restrict__ poi, int NPOI,
                                    float* __restrict__ out_loc,
                                    float* __restrict__ out_time,
                                    int L) {
    __shared__ float sE[L_MAX];
    __shared__ float sProw[NT_MAX];
    __shared__ float red[32];
    int s = blockIdx.x;
    int tid = threadIdx.x;
    int c = cur[s];
    int ct = cur_t[s];
    if (tid < NT_MAX) sProw[tid] = g_P[ct * NT_MAX + tid];
    const float* prow = poi + (size_t)c * NPOI;

    float lmax = -INFINITY;
    for (int l = tid; l < L; l += blockDim.x) {
        float d = __ldg(&prow[his[l]]);
        float e = (d != 0.f) ? (1.0f / d) : 1e-6f;
        sE[l] = e;
        lmax = fmaxf(lmax, e);
    }
    float mx = block_reduce(lmax, true, red);

    float lsum = 0.f;
    for (int l = tid; l < L; l += blockDim.x) {
        float v = __expf(sE[l] - mx);
        sE[l] = v;
        lsum += v;
    }
    float inv = 1.0f / block_reduce(lsum, false, red);

    float* ol = out_loc  + (size_t)s * L;
    float* ot = out_time + (size_t)s * L;
    for (int l = tid; l < L; l += blockDim.x) {
        ol[l] = sE[l] * inv;
        ot[l] = sProw[his_t[l]];
    }
}

// ---------------------------------------------------------------------------
// Kernel 4: E = w1 * (user_emb @ id_emb^T) + w2 * bias[l]
// NT-GEMM (both operands row-major [rows, K]), 128x128 tile, 8x8 per thread.
// ---------------------------------------------------------------------------
#define BM 128
#define BN 128
#define BK 16
#define TM 8
#define TN 8

__global__ __launch_bounds__(256) void gemm_user_kernel(
    const float* __restrict__ A,   // [M, K] user_emb
    const float* __restrict__ B,   // [N, K] id_emb
    const float* __restrict__ w1p, const float* __restrict__ w2p,
    float* __restrict__ E, int M, int N, int K) {
    __shared__ float As[BK][BM];
    __shared__ float Bs[BK][BN];
    int tid = threadIdx.x;
    int bm = blockIdx.y * BM;
    int bn = blockIdx.x * BN;
    int ty = tid >> 4, tx = tid & 15;

    float acc[TM][TN];
    #pragma unroll
    for (int i = 0; i < TM; ++i)
        #pragma unroll
        for (int j = 0; j < TN; ++j) acc[i][j] = 0.f;

    for (int k0 = 0; k0 < K; k0 += BK) {
        #pragma unroll
        for (int i = 0; i < 2; ++i) {
            int idx = tid + i * 256;        // 0..511
            int row = idx >> 2;             // 0..127
            int c4  = (idx & 3) << 2;       // 0,4,8,12
            int gk  = k0 + c4;
            float4 va = make_float4(0.f, 0.f, 0.f, 0.f);
            float4 vb = make_float4(0.f, 0.f, 0.f, 0.f);
            if (gk + 3 < K) {
                va = *(const float4*)(A + (size_t)(bm + row) * K + gk);
                vb = *(const float4*)(B + (size_t)(bn + row) * K + gk);
            } else {
                const float* ap = A + (size_t)(bm + row) * K;
                const float* bp = B + (size_t)(bn + row) * K;
                if (gk + 0 < K) { va.x = ap[gk + 0]; vb.x = bp[gk + 0]; }
                if (gk + 1 < K) { va.y = ap[gk + 1]; vb.y = bp[gk + 1]; }
                if (gk + 2 < K) { va.z = ap[gk + 2]; vb.z = bp[gk + 2]; }
                if (gk + 3 < K) { va.w = ap[gk + 3]; vb.w = bp[gk + 3]; }
            }
            As[c4 + 0][row] = va.x; As[c4 + 1][row] = va.y;
            As[c4 + 2][row] = va.z; As[c4 + 3][row] = va.w;
            Bs[c4 + 0][row] = vb.x; Bs[c4 + 1][row] = vb.y;
            Bs[c4 + 2][row] = vb.z; Bs[c4 + 3][row] = vb.w;
        }
        __syncthreads();
        #pragma unroll
        for (int kk = 0; kk < BK; ++kk) {
            float ra[TM], rb[TN];
            *(float4*)&ra[0] = *(const float4*)&As[kk][ty * TM];
            *(float4*)&ra[4] = *(const float4*)&As[kk][ty * TM + 4];
            *(float4*)&rb[0] = *(const float4*)&Bs[kk][tx * TN];
            *(float4*)&rb[4] = *(const float4*)&Bs[kk][tx * TN + 4];
            #pragma unroll
            for (int i = 0; i < TM; ++i)
                #pragma unroll
                for (int j = 0; j < TN; ++j)
                    acc[i][j] = fmaf(ra[i], rb[j], acc[i][j]);
        }
        __syncthreads();
    }

    float w1 = *w1p, w2 = *w2p;
    #pragma unroll
    for (int i = 0; i < TM; ++i) {
        int r = bm + ty * TM + i;
        float vals[TN];
        #pragma unroll
        for (int j = 0; j < TN; ++j) {
            int cidx = bn + tx * TN + j;
            vals[j] = fmaf(w1, acc[i][j], w2 * g_bias[cidx]);
        }
        float* ep = E + (size_t)r * N + bn + tx * TN;
        *(float4*)(ep + 0) = make_float4(vals[0], vals[1], vals[2], vals[3]);
        *(float4*)(ep + 4) = make_float4(vals[4], vals[5], vals[6], vals[7]);
    }
}

// ---------------------------------------------------------------------------
// Kernel 5: in-place row softmax over the user-energy slab.
// ---------------------------------------------------------------------------
__global__ void row_softmax_kernel(float* __restrict__ E, int L) {
    __shared__ float sE[L_MAX];
    __shared__ float red[32];
    int tid = threadIdx.x;
    float* row = E + (size_t)blockIdx.x * L;

    float lmax = -INFINITY;
    for (int l = tid; l < L; l += blockDim.x) {
        float v = row[l];
        sE[l] = v;
        lmax = fmaxf(lmax, v);
    }
    float mx = block_reduce(lmax, true, red);

    float lsum = 0.f;
    for (int l = tid; l < L; l += blockDim.x) {
        float v = __expf(sE[l] - mx);
        sE[l] = v;
        lsum += v;
    }
    float inv = 1.0f / block_reduce(lsum, false, red);

    for (int l = tid; l < L; l += blockDim.x)
        row[l] = sE[l] * inv;
}

// ---------------------------------------------------------------------------
// launch
// ---------------------------------------------------------------------------
extern "C" void kernel_launch(void* const* d_in, const int* in_sizes, int n_in,
                              void* d_out, int out_size) {
    const int*   his   = (const int*)d_in[0];
    const int*   cur   = (const int*)d_in[1];
    const int*   his_t = (const int*)d_in[2];
    const int*   cur_t = (const int*)d_in[3];
    const float* poi   = (const float*)d_in[4];
    const float* tsim  = (const float*)d_in[5];
    const float* uemb  = (const float*)d_in[6];
    const float* iemb  = (const float*)d_in[7];
    const float* soc   = (const float*)d_in[8];
    const float* w1    = (const float*)d_in[9];
    const float* w2    = (const float*)d_in[10];

    int L = in_sizes[0];
    int S = in_sizes[1];
    int D = in_sizes[8];
    int NPOI = (int)(sqrt((double)in_sizes[4]) + 0.5);
    int NT   = (int)(sqrt((double)in_sizes[5]) + 0.5);

    float* out      = (float*)d_out;
    float* out_loc  = out;
    float* out_time = out + (size_t)S * L;
    float* out_user = out + 2 * (size_t)S * L;

    time_table_kernel<<<1, 256>>>(his_t, L, tsim, NT);
    bias_kernel<<<(L + 7) / 8, 256>>>(iemb, soc, L, D);
    row_loc_time_kernel<<<S, 256>>>(his, cur, his_t, cur_t, poi, NPOI,
                                    out_loc, out_time, L);
    dim3 grid(L / BN, S / BM);
    gemm_user_kernel<<<grid, 256>>>(uemb, iemb, w1, w2, out_user, S, L, D);
    row_softmax_kernel<<<S, 256>>>(out_user, L);
}

// round 7
// speedup vs baseline: 1.7863x; 1.7863x over previous
#include <cuda_runtime.h>
#include <cuda_bf16.h>
#include <math.h>
#include <stdint.h>

#define NT_MAX 64
#define L_MAX  4096
#define SV     2048      // S
#define LV     4096      // L
#define KP     512       // padded K for GEMM

__device__ float g_P[NT_MAX * NT_MAX];   // time softmax table P[r][t]
__device__ float g_bias[L_MAX];          // id_emb @ socail_uid_emb

// bf16 hi/lo splits of user_emb (A) and id_emb (B), K padded to 512 with zeros
__device__ __nv_bfloat16 g_Ahi[SV * KP];
__device__ __nv_bfloat16 g_Alo[SV * KP];
__device__ __nv_bfloat16 g_Bhi[LV * KP];
__device__ __nv_bfloat16 g_Blo[LV * KP];

// ---------------------------------------------------------------------------
// PTX helpers (sm_80-era only: ldmatrix / mma.sync / cp.async — compute_100 OK)
// ---------------------------------------------------------------------------
__device__ __forceinline__ uint32_t smem_u32(const void* p) {
    uint32_t a;
    asm("{ .reg .u64 t; cvta.to.shared.u64 t, %1; cvt.u32.u64 %0, t; }"
        : "=r"(a) : "l"(p));
    return a;
}
__device__ __forceinline__ void ldsm_x4(uint32_t& r0, uint32_t& r1,
                                        uint32_t& r2, uint32_t& r3, uint32_t a) {
    asm volatile("ldmatrix.sync.aligned.m8n8.x4.shared.b16 {%0,%1,%2,%3}, [%4];"
                 : "=r"(r0), "=r"(r1), "=r"(r2), "=r"(r3) : "r"(a));
}
__device__ __forceinline__ void mma16816(float* d, const uint32_t* a, const uint32_t* b) {
    asm volatile(
        "mma.sync.aligned.m16n8k16.row.col.f32.bf16.bf16.f32 "
        "{%0,%1,%2,%3}, {%4,%5,%6,%7}, {%8,%9}, {%0,%1,%2,%3};"
        : "+f"(d[0]), "+f"(d[1]), "+f"(d[2]), "+f"(d[3])
        : "r"(a[0]), "r"(a[1]), "r"(a[2]), "r"(a[3]), "r"(b[0]), "r"(b[1]));
}
__device__ __forceinline__ void cp16(uint32_t s, const void* g) {
    asm volatile("cp.async.cg.shared.global [%0], [%1], 16;"
                 :: "r"(s), "l"(g) : "memory");
}
#define CP_COMMIT() asm volatile("cp.async.commit_group;" ::: "memory")
#define CP_WAIT1()  asm volatile("cp.async.wait_group 1;" ::: "memory")

// ---------------------------------------------------------------------------
// Kernel: split fp32 -> bf16 hi/lo, zero-padding K from D to KP
// ---------------------------------------------------------------------------
__global__ void split_bf16_kernel(const float* __restrict__ src, int rows, int D, int which) {
    int idx = blockIdx.x * blockDim.x + threadIdx.x;
    int total = rows * KP;
    if (idx >= total) return;
    int r = idx / KP, c = idx % KP;
    float x = (c < D) ? src[(size_t)r * D + c] : 0.f;
    __nv_bfloat16 hi = __float2bfloat16(x);
    __nv_bfloat16 lo = __float2bfloat16(x - __bfloat162float(hi));
    if (which == 0) { g_Ahi[idx] = hi; g_Alo[idx] = lo; }
    else            { g_Bhi[idx] = hi; g_Blo[idx] = lo; }
}

// ---------------------------------------------------------------------------
// Kernel 1: 48x48 time-attention table via histogram factorization.
// ---------------------------------------------------------------------------
__global__ void time_table_kernel(const int* __restrict__ his_t, int L,
                                  const float* __restrict__ T, int NT) {
    __shared__ int scnt[NT_MAX];
    int tid = threadIdx.x;
    if (tid < NT_MAX) scnt[tid] = 0;
    __syncthreads();
    for (int l = tid; l < L; l += blockDim.x)
        atomicAdd(&scnt[his_t[l]], 1);
    __syncthreads();
    if (tid < NT) {
        int r = tid;
        float mx = -INFINITY;
        for (int t = 0; t < NT; ++t)
            if (scnt[t] > 0) mx = fmaxf(mx, T[r * NT + t]);
        float denom = 0.f;
        for (int t = 0; t < NT; ++t)
            if (scnt[t] > 0) denom += (float)scnt[t] * __expf(T[r * NT + t] - mx);
        float inv = 1.0f / denom;
        for (int t = 0; t < NT; ++t)
            g_P[r * NT_MAX + t] = __expf(T[r * NT + t] - mx) * inv;
    }
}

// ---------------------------------------------------------------------------
// Kernel 2: bias[l] = id_emb[l] . socail_uid_emb   (one warp per row)
// ---------------------------------------------------------------------------
__global__ void bias_kernel(const float* __restrict__ id_emb,
                            const float* __restrict__ soc, int L, int D) {
    int warp = (blockIdx.x * blockDim.x + threadIdx.x) >> 5;
    int lane = threadIdx.x & 31;
    if (warp >= L) return;
    const float* row = id_emb + (size_t)warp * D;
    float s = 0.f;
    for (int k = lane; k < D; k += 32) s += row[k] * soc[k];
    #pragma unroll
    for (int o = 16; o; o >>= 1) s += __shfl_xor_sync(0xffffffffu, s, o);
    if (lane == 0) g_bias[warp] = s;
}

// ---------------------------------------------------------------------------
// block-wide reduce (max or sum)
// ---------------------------------------------------------------------------
__device__ __forceinline__ float block_reduce(float v, bool is_max, float* red) {
    int lane = threadIdx.x & 31, wid = threadIdx.x >> 5;
    #pragma unroll
    for (int o = 16; o; o >>= 1) {
        float u = __shfl_xor_sync(0xffffffffu, v, o);
        v = is_max ? fmaxf(v, u) : (v + u);
    }
    __syncthreads();
    if (lane == 0) red[wid] = v;
    __syncthreads();
    int nw = blockDim.x >> 5;
    if (wid == 0) {
        float x = (lane < nw) ? red[lane] : (is_max ? -INFINITY : 0.f);
        #pragma unroll
        for (int o = 16; o; o >>= 1) {
            float u = __shfl_xor_sync(0xffffffffu, x, o);
            x = is_max ? fmaxf(x, u) : (x + u);
        }
        if (lane == 0) red[0] = x;
    }
    __syncthreads();
    return red[0];
}

// ---------------------------------------------------------------------------
// Kernel 3: per-row attn_loc (gather + softmax) and attn_time (table gather)
// ---------------------------------------------------------------------------
__global__ void row_loc_time_kernel(const int* __restrict__ his,
                                    const int* __restrict__ cur,
                                    const int* __restrict__ his_t,
                                    const int* __restrict__ cur_t,
                                    const float* __restrict__ poi, int NPOI,
                                    float* __restrict__ out_loc,
                                    float* __restrict__ out_time, int L) {
    __shared__ float sE[L_MAX];
    __shared__ float sProw[NT_MAX];
    __shared__ float red[32];
    int s = blockIdx.x;
    int tid = threadIdx.x;
    int c = cur[s];
    int ct = cur_t[s];
    if (tid < NT_MAX) sProw[tid] = g_P[ct * NT_MAX + tid];
    const float* prow = poi + (size_t)c * NPOI;

    float lmax = -INFINITY;
    for (int l = tid; l < L; l += blockDim.x) {
        float d = __ldg(&prow[his[l]]);
        float e = (d != 0.f) ? (1.0f / d) : 1e-6f;
        sE[l] = e;
        lmax = fmaxf(lmax, e);
    }
    float mx = block_reduce(lmax, true, red);

    float lsum = 0.f;
    for (int l = tid; l < L; l += blockDim.x) {
        float v = __expf(sE[l] - mx);
        sE[l] = v;
        lsum += v;
    }
    float inv = 1.0f / block_reduce(lsum, false, red);

    float* ol = out_loc  + (size_t)s * L;
    float* ot = out_time + (size_t)s * L;
    for (int l = tid; l < L; l += blockDim.x) {
        ol[l] = sE[l] * inv;
        ot[l] = sProw[his_t[l]];
    }
}

// ---------------------------------------------------------------------------
// Kernel 4: tensor-core GEMM via mma.sync (bf16 3-term split, fp32 accum)
//   E = w1 * (A @ B^T) + w2 * bias
// CTA 128x128, BK=32, 8 warps (warp tile 32x64), 3-stage cp.async pipeline.
// Smem: per stage A[128][32] + B[128][32] bf16, 64B rows, SW64-style swizzle:
//   16B-chunk c' = c ^ ((row>>1)&3)  -> conflict-free cp.async stores & ldmatrix.
// ---------------------------------------------------------------------------
#define GBM 128
#define GBN 128
#define GBK 32
#define STAGES 3
#define STAGE_BYTES 16384      // A 8KB + B 8KB
#define NITER 48               // 3 terms x (512/32)

__global__ __launch_bounds__(256, 2)
void gemm_mma_kernel(const float* __restrict__ w1p, const float* __restrict__ w2p,
                     float* __restrict__ E, int L) {
    __shared__ __align__(16) char smem[STAGES * STAGE_BYTES];
    uint32_t sbase = smem_u32(smem);
    int tid = threadIdx.x;
    int wid = tid >> 5, lane = tid & 31;
    int bm = blockIdx.y * GBM;
    int bn = blockIdx.x * GBN;
    int warp_m = wid & 3;      // 4 warps along M (32 rows each)
    int warp_n = wid >> 2;     // 2 warps along N (64 cols each)

    float acc[2][8][4];
    #pragma unroll
    for (int i = 0; i < 2; ++i)
        #pragma unroll
        for (int j = 0; j < 8; ++j)
            #pragma unroll
            for (int k = 0; k < 4; ++k) acc[i][j][k] = 0.f;

    // prefetch of BK=32 slab for virtual iter i (term = i/16, k0 = (i%16)*32)
    auto prefetch = [&](int i) {
        int term = i >> 4;
        int k0 = (i & 15) * GBK;
        const __nv_bfloat16* Ag = (term == 2) ? g_Alo : g_Ahi;
        const __nv_bfloat16* Bg = (term == 1) ? g_Blo : g_Bhi;
        uint32_t st = sbase + (uint32_t)(i % STAGES) * STAGE_BYTES;
        #pragma unroll
        for (int j = 0; j < 2; ++j) {
            int idx = tid + j * 256;          // 0..511
            int r = idx >> 2, c = idx & 3;    // row, 16B chunk
            uint32_t so = (uint32_t)(r * 64 + ((c ^ ((r >> 1) & 3)) << 4));
            cp16(st + so,        Ag + (size_t)(bm + r) * KP + k0 + c * 8);
            cp16(st + so + 8192, Bg + (size_t)(bn + r) * KP + k0 + c * 8);
        }
    };

    prefetch(0); CP_COMMIT();
    prefetch(1); CP_COMMIT();

    for (int i = 0; i < NITER; ++i) {
        CP_WAIT1();            // stage i resident
        __syncthreads();       // ...for all threads; stage i-1 compute done
        if (i + 2 < NITER) prefetch(i + 2);
        CP_COMMIT();

        uint32_t aB = sbase + (uint32_t)(i % STAGES) * STAGE_BYTES;
        uint32_t bB = aB + 8192;

        #pragma unroll
        for (int ks = 0; ks < 2; ++ks) {       // two k16 steps in BK=32
            uint32_t a[2][4];
            #pragma unroll
            for (int mt = 0; mt < 2; ++mt) {
                int r = warp_m * 32 + mt * 16 + (lane & 15);
                int kc = ks * 2 + (lane >> 4);
                uint32_t addr = aB + r * 64 + ((kc ^ ((r >> 1) & 3)) << 4);
                ldsm_x4(a[mt][0], a[mt][1], a[mt][2], a[mt][3], addr);
            }
            uint32_t b[8][2];
            #pragma unroll
            for (int tp = 0; tp < 4; ++tp) {   // n8-tile pair (2tp, 2tp+1)
                int g = lane >> 3;
                int nr = warp_n * 64 + (2 * tp + (g >> 1)) * 8 + (lane & 7);
                int kc = ks * 2 + (g & 1);
                uint32_t addr = bB + nr * 64 + ((kc ^ ((nr >> 1) & 3)) << 4);
                uint32_t r0, r1, r2, r3;
                ldsm_x4(r0, r1, r2, r3, addr);
                b[2 * tp][0] = r0; b[2 * tp][1] = r1;
                b[2 * tp + 1][0] = r2; b[2 * tp + 1][1] = r3;
            }
            #pragma unroll
            for (int mt = 0; mt < 2; ++mt)
                #pragma unroll
                for (int nt = 0; nt < 8; ++nt)
                    mma16816(acc[mt][nt], a[mt], b[nt]);
        }
        __syncthreads();       // done reading stage before it is overwritten
    }

    // epilogue: out = w1*acc + w2*bias[col]; direct float2 stores
    float w1 = *w1p, w2 = *w2p;
    int qr = lane >> 2;              // 0..7
    int qc = (lane & 3) * 2;
    #pragma unroll
    for (int nt = 0; nt < 8; ++nt) {
        int col = bn + warp_n * 64 + nt * 8 + qc;
        float2 bv = *(const float2*)(g_bias + col);
        float bx = w2 * bv.x, by = w2 * bv.y;
        #pragma unroll
        for (int mt = 0; mt < 2; ++mt) {
            int row0 = bm + warp_m * 32 + mt * 16 + qr;
            float2 v0 = make_float2(fmaf(w1, acc[mt][nt][0], bx),
                                    fmaf(w1, acc[mt][nt][1], by));
            float2 v1 = make_float2(fmaf(w1, acc[mt][nt][2], bx),
                                    fmaf(w1, acc[mt][nt][3], by));
            *(float2*)(E + (size_t)row0 * L + col)       = v0;
            *(float2*)(E + (size_t)(row0 + 8) * L + col) = v1;
        }
    }
}

// ---------------------------------------------------------------------------
// Kernel 5: in-place row softmax over the user-energy slab.
// ---------------------------------------------------------------------------
__global__ void row_softmax_kernel(float* __restrict__ E, int L) {
    __shared__ float sE[L_MAX];
    __shared__ float red[32];
    int tid = threadIdx.x;
    float* row = E + (size_t)blockIdx.x * L;

    float lmax = -INFINITY;
    for (int l = tid; l < L; l += blockDim.x) {
        float v = row[l];
        sE[l] = v;
        lmax = fmaxf(lmax, v);
    }
    float mx = block_reduce(lmax, true, red);

    float lsum = 0.f;
    for (int l = tid; l < L; l += blockDim.x) {
        float v = __expf(sE[l] - mx);
        sE[l] = v;
        lsum += v;
    }
    float inv = 1.0f / block_reduce(lsum, false, red);

    for (int l = tid; l < L; l += blockDim.x)
        row[l] = sE[l] * inv;
}

// ---------------------------------------------------------------------------
// launch
// ---------------------------------------------------------------------------
extern "C" void kernel_launch(void* const* d_in, const int* in_sizes, int n_in,
                              void* d_out, int out_size) {
    const int*   his   = (const int*)d_in[0];
    const int*   cur   = (const int*)d_in[1];
    const int*   his_t = (const int*)d_in[2];
    const int*   cur_t = (const int*)d_in[3];
    const float* poi   = (const float*)d_in[4];
    const float* tsim  = (const float*)d_in[5];
    const float* uemb  = (const float*)d_in[6];
    const float* iemb  = (const float*)d_in[7];
    const float* soc   = (const float*)d_in[8];
    const float* w1    = (const float*)d_in[9];
    const float* w2    = (const float*)d_in[10];

    int L = in_sizes[0];
    int S = in_sizes[1];
    int D = in_sizes[8];
    int NPOI = (int)(sqrt((double)in_sizes[4]) + 0.5);
    int NT   = (int)(sqrt((double)in_sizes[5]) + 0.5);

    float* out      = (float*)d_out;
    float* out_loc  = out;
    float* out_time = out + (size_t)S * L;
    float* out_user = out + 2 * (size_t)S * L;

    time_table_kernel<<<1, 256>>>(his_t, L, tsim, NT);
    bias_kernel<<<(L + 7) / 8, 256>>>(iemb, soc, L, D);

    split_bf16_kernel<<<(S * KP + 255) / 256, 256>>>(uemb, S, D, 0);
    split_bf16_kernel<<<(L * KP + 255) / 256, 256>>>(iemb, L, D, 1);

    row_loc_time_kernel<<<S, 256>>>(his, cur, his_t, cur_t, poi, NPOI,
                                    out_loc, out_time, L);

    dim3 grid(L / GBN, S / GBM);
    gemm_mma_kernel<<<grid, 256>>>(w1, w2, out_user, L);

    row_softmax_kernel<<<S, 256>>>(out_user, L);
}

// round 8
// speedup vs baseline: 1.9403x; 1.0862x over previous
#include <cuda_runtime.h>
#include <cuda_bf16.h>
#include <math.h>
#include <stdint.h>

#define NT_MAX 64
#define L_MAX  4096
#define SV     2048      // S
#define LV     4096      // L
#define KP     512       // padded K for GEMM

__device__ float g_P[NT_MAX * NT_MAX];   // time softmax table P[r][t]
__device__ float g_bias[L_MAX];          // id_emb @ socail_uid_emb

// bf16 hi/lo splits of user_emb (A) and id_emb (B), K padded to 512 with zeros
__device__ __nv_bfloat16 g_Ahi[SV * KP];
__device__ __nv_bfloat16 g_Alo[SV * KP];
__device__ __nv_bfloat16 g_Bhi[LV * KP];
__device__ __nv_bfloat16 g_Blo[LV * KP];

// ---------------------------------------------------------------------------
// PTX helpers (sm_80-era only: ldmatrix / mma.sync / cp.async — compute_100 OK)
// ---------------------------------------------------------------------------
__device__ __forceinline__ uint32_t smem_u32(const void* p) {
    uint32_t a;
    asm("{ .reg .u64 t; cvta.to.shared.u64 t, %1; cvt.u32.u64 %0, t; }"
        : "=r"(a) : "l"(p));
    return a;
}
__device__ __forceinline__ void ldsm_x4(uint32_t& r0, uint32_t& r1,
                                        uint32_t& r2, uint32_t& r3, uint32_t a) {
    asm volatile("ldmatrix.sync.aligned.m8n8.x4.shared.b16 {%0,%1,%2,%3}, [%4];"
                 : "=r"(r0), "=r"(r1), "=r"(r2), "=r"(r3) : "r"(a));
}
__device__ __forceinline__ void mma16816(float* d, const uint32_t* a, const uint32_t* b) {
    asm volatile(
        "mma.sync.aligned.m16n8k16.row.col.f32.bf16.bf16.f32 "
        "{%0,%1,%2,%3}, {%4,%5,%6,%7}, {%8,%9}, {%0,%1,%2,%3};"
        : "+f"(d[0]), "+f"(d[1]), "+f"(d[2]), "+f"(d[3])
        : "r"(a[0]), "r"(a[1]), "r"(a[2]), "r"(a[3]), "r"(b[0]), "r"(b[1]));
}
__device__ __forceinline__ void cp16(uint32_t s, const void* g) {
    asm volatile("cp.async.cg.shared.global [%0], [%1], 16;"
                 :: "r"(s), "l"(g) : "memory");
}
#define CP_COMMIT() asm volatile("cp.async.commit_group;" ::: "memory")
#define CP_WAIT2()  asm volatile("cp.async.wait_group 2;" ::: "memory")

// ---------------------------------------------------------------------------
// Kernel A: fused split fp32 -> bf16 hi/lo for user_emb AND id_emb.
// Vectorized: each thread handles 8 consecutive elements (float4 x2 in,
// uint4 x2 out). K padded D -> KP with zeros.
// ---------------------------------------------------------------------------
__global__ void split_bf16_kernel(const float* __restrict__ Asrc,
                                  const float* __restrict__ Bsrc, int D) {
    int idx = blockIdx.x * blockDim.x + threadIdx.x;
    const int CPR = KP / 8;                 // chunks per row = 64
    const int chunksA = SV * CPR;
    const float* src;
    __nv_bfloat16 *hid, *lod;
    if (idx < chunksA) {
        src = Asrc; hid = g_Ahi; lod = g_Alo;
    } else {
        idx -= chunksA;
        if (idx >= LV * CPR) return;
        src = Bsrc; hid = g_Bhi; lod = g_Blo;
    }
    int r = idx / CPR, c = (idx % CPR) * 8;

    float v[8];
    if (c + 7 < D) {
        float4 a = *(const float4*)(src + (size_t)r * D + c);
        float4 b = *(const float4*)(src + (size_t)r * D + c + 4);
        v[0] = a.x; v[1] = a.y; v[2] = a.z; v[3] = a.w;
        v[4] = b.x; v[5] = b.y; v[6] = b.z; v[7] = b.w;
    } else {
        #pragma unroll
        for (int j = 0; j < 8; ++j)
            v[j] = (c + j < D) ? src[(size_t)r * D + c + j] : 0.f;
    }

    uint32_t hp[4], lp[4];
    #pragma unroll
    for (int j = 0; j < 4; ++j) {
        __nv_bfloat16 h0 = __float2bfloat16(v[2 * j]);
        __nv_bfloat16 h1 = __float2bfloat16(v[2 * j + 1]);
        __nv_bfloat16 l0 = __float2bfloat16(v[2 * j]     - __bfloat162float(h0));
        __nv_bfloat16 l1 = __float2bfloat16(v[2 * j + 1] - __bfloat162float(h1));
        hp[j] = (uint32_t)*(const uint16_t*)&h0 | ((uint32_t)*(const uint16_t*)&h1 << 16);
        lp[j] = (uint32_t)*(const uint16_t*)&l0 | ((uint32_t)*(const uint16_t*)&l1 << 16);
    }
    *(uint4*)(hid + (size_t)r * KP + c) = make_uint4(hp[0], hp[1], hp[2], hp[3]);
    *(uint4*)(lod + (size_t)r * KP + c) = make_uint4(lp[0], lp[1], lp[2], lp[3]);
}

// ---------------------------------------------------------------------------
// Kernel B (fused prep): blocks [0, L/8) compute bias rows (one warp per row);
// the last block builds the 48x48 time-attention table via the his_t histogram.
// ---------------------------------------------------------------------------
__global__ void prep_kernel(const int* __restrict__ his_t, int L,
                            const float* __restrict__ T, int NT,
                            const float* __restrict__ id_emb,
                            const float* __restrict__ soc, int D) {
    if ((int)blockIdx.x == (int)gridDim.x - 1) {
        __shared__ int scnt[NT_MAX];
        int tid = threadIdx.x;
        if (tid < NT_MAX) scnt[tid] = 0;
        __syncthreads();
        for (int l = tid; l < L; l += blockDim.x)
            atomicAdd(&scnt[his_t[l]], 1);
        __syncthreads();
        if (tid < NT) {
            int r = tid;
            float mx = -INFINITY;
            for (int t = 0; t < NT; ++t)
                if (scnt[t] > 0) mx = fmaxf(mx, T[r * NT + t]);
            float denom = 0.f;
            for (int t = 0; t < NT; ++t)
                if (scnt[t] > 0) denom += (float)scnt[t] * __expf(T[r * NT + t] - mx);
            float inv = 1.0f / denom;
            for (int t = 0; t < NT; ++t)
                g_P[r * NT_MAX + t] = __expf(T[r * NT + t] - mx) * inv;
        }
        return;
    }
    int warp = (blockIdx.x * blockDim.x + threadIdx.x) >> 5;
    int lane = threadIdx.x & 31;
    if (warp >= L) return;
    const float* row = id_emb + (size_t)warp * D;
    float s = 0.f;
    for (int k = lane; k < D; k += 32) s += row[k] * soc[k];
    #pragma unroll
    for (int o = 16; o; o >>= 1) s += __shfl_xor_sync(0xffffffffu, s, o);
    if (lane == 0) g_bias[warp] = s;
}

// ---------------------------------------------------------------------------
// block-wide reduce (max or sum)
// ---------------------------------------------------------------------------
__device__ __forceinline__ float block_reduce(float v, bool is_max, float* red) {
    int lane = threadIdx.x & 31, wid = threadIdx.x >> 5;
    #pragma unroll
    for (int o = 16; o; o >>= 1) {
        float u = __shfl_xor_sync(0xffffffffu, v, o);
        v = is_max ? fmaxf(v, u) : (v + u);
    }
    __syncthreads();
    if (lane == 0) red[wid] = v;
    __syncthreads();
    int nw = blockDim.x >> 5;
    if (wid == 0) {
        float x = (lane < nw) ? red[lane] : (is_max ? -INFINITY : 0.f);
        #pragma unroll
        for (int o = 16; o; o >>= 1) {
            float u = __shfl_xor_sync(0xffffffffu, x, o);
            x = is_max ? fmaxf(x, u) : (x + u);
        }
        if (lane == 0) red[0] = x;
    }
    __syncthreads();
    return red[0];
}

// ---------------------------------------------------------------------------
// Kernel C: per-row attn_loc (gather + softmax) and attn_time (table gather)
// ---------------------------------------------------------------------------
__global__ void row_loc_time_kernel(const int* __restrict__ his,
                                    const int* __restrict__ cur,
                                    const int* __restrict__ his_t,
                                    const int* __restrict__ cur_t,
                                    const float* __restrict__ poi, int NPOI,
                                    float* __restrict__ out_loc,
                                    float* __restrict__ out_time, int L) {
    __shared__ float sE[L_MAX];
    __shared__ float sProw[NT_MAX];
    __shared__ float red[32];
    int s = blockIdx.x;
    int tid = threadIdx.x;
    int c = cur[s];
    int ct = cur_t[s];
    if (tid < NT_MAX) sProw[tid] = g_P[ct * NT_MAX + tid];
    const float* prow = poi + (size_t)c * NPOI;

    float lmax = -INFINITY;
    for (int l = tid; l < L; l += blockDim.x) {
        float d = __ldg(&prow[his[l]]);
        float e = (d != 0.f) ? (1.0f / d) : 1e-6f;
        sE[l] = e;
        lmax = fmaxf(lmax, e);
    }
    float mx = block_reduce(lmax, true, red);

    float lsum = 0.f;
    for (int l = tid; l < L; l += blockDim.x) {
        float v = __expf(sE[l] - mx);
        sE[l] = v;
        lsum += v;
    }
    float inv = 1.0f / block_reduce(lsum, false, red);

    float* ol = out_loc  + (size_t)s * L;
    float* ot = out_time + (size_t)s * L;
    for (int l = tid; l < L; l += blockDim.x) {
        ol[l] = sE[l] * inv;
        ot[l] = sProw[his_t[l]];
    }
}

// ---------------------------------------------------------------------------
// Kernel D: tensor-core GEMM via mma.sync (bf16 3-term split, fp32 accum)
//   E = w1 * (A @ B^T) + w2 * bias
// CTA 128x128, BK=32, 8 warps (warp tile 32x64), 4-stage cp.async pipeline,
// ONE __syncthreads per iteration. SW64-style swizzle on 16B chunks.
// ---------------------------------------------------------------------------
#define GBM 128
#define GBN 128
#define GBK 32
#define STAGES 4
#define STAGE_BYTES 16384      // A 8KB + B 8KB
#define GEMM_SMEM (STAGES * STAGE_BYTES)
#define NITER 48               // 3 terms x (512/32)

__global__ __launch_bounds__(256)
void gemm_mma_kernel(const float* __restrict__ w1p, const float* __restrict__ w2p,
                     float* __restrict__ E, int L) {
    extern __shared__ __align__(16) char smem[];
    uint32_t sbase = smem_u32(smem);
    int tid = threadIdx.x;
    int wid = tid >> 5, lane = tid & 31;
    int bm = blockIdx.y * GBM;
    int bn = blockIdx.x * GBN;
    int warp_m = wid & 3;      // 4 warps along M (32 rows each)
    int warp_n = wid >> 2;     // 2 warps along N (64 cols each)

    float acc[2][8][4];
    #pragma unroll
    for (int i = 0; i < 2; ++i)
        #pragma unroll
        for (int j = 0; j < 8; ++j)
            #pragma unroll
            for (int k = 0; k < 4; ++k) acc[i][j][k] = 0.f;

    // prefetch BK=32 slab for virtual iter i (term = i/16, k0 = (i%16)*32)
    auto prefetch = [&](int i) {
        int term = i >> 4;
        int k0 = (i & 15) * GBK;
        const __nv_bfloat16* Ag = (term == 2) ? g_Alo : g_Ahi;
        const __nv_bfloat16* Bg = (term == 1) ? g_Blo : g_Bhi;
        uint32_t st = sbase + (uint32_t)(i % STAGES) * STAGE_BYTES;
        #pragma unroll
        for (int j = 0; j < 2; ++j) {
            int idx = tid + j * 256;          // 0..511
            int r = idx >> 2, c = idx & 3;    // row, 16B chunk
            uint32_t so = (uint32_t)(r * 64 + ((c ^ ((r >> 1) & 3)) << 4));
            cp16(st + so,        Ag + (size_t)(bm + r) * KP + k0 + c * 8);
            cp16(st + so + 8192, Bg + (size_t)(bn + r) * KP + k0 + c * 8);
        }
    };

    prefetch(0); CP_COMMIT();
    prefetch(1); CP_COMMIT();
    prefetch(2); CP_COMMIT();

    for (int i = 0; i < NITER; ++i) {
        CP_WAIT2();            // stage i (and i+1) resident; <=2 groups pending
        __syncthreads();       // also orders iter i-1 reads before overwrite
        if (i + 3 < NITER) prefetch(i + 3);
        CP_COMMIT();

        uint32_t aB = sbase + (uint32_t)(i % STAGES) * STAGE_BYTES;
        uint32_t bB = aB + 8192;

        #pragma unroll
        for (int ks = 0; ks < 2; ++ks) {       // two k16 steps in BK=32
            uint32_t a[2][4];
            #pragma unroll
            for (int mt = 0; mt < 2; ++mt) {
                int r = warp_m * 32 + mt * 16 + (lane & 15);
                int kc = ks * 2 + (lane >> 4);
                uint32_t addr = aB + r * 64 + ((kc ^ ((r >> 1) & 3)) << 4);
                ldsm_x4(a[mt][0], a[mt][1], a[mt][2], a[mt][3], addr);
            }
            uint32_t b[8][2];
            #pragma unroll
            for (int tp = 0; tp < 4; ++tp) {   // n8-tile pair (2tp, 2tp+1)
                int g = lane >> 3;
                int nr = warp_n * 64 + (2 * tp + (g >> 1)) * 8 + (lane & 7);
                int kc = ks * 2 + (g & 1);
                uint32_t addr = bB + nr * 64 + ((kc ^ ((nr >> 1) & 3)) << 4);
                uint32_t r0, r1, r2, r3;
                ldsm_x4(r0, r1, r2, r3, addr);
                b[2 * tp][0] = r0; b[2 * tp][1] = r1;
                b[2 * tp + 1][0] = r2; b[2 * tp + 1][1] = r3;
            }
            #pragma unroll
            for (int mt = 0; mt < 2; ++mt)
                #pragma unroll
                for (int nt = 0; nt < 8; ++nt)
                    mma16816(acc[mt][nt], a[mt], b[nt]);
        }
    }

    // epilogue: out = w1*acc + w2*bias[col]; direct float2 stores
    float w1 = *w1p, w2 = *w2p;
    int qr = lane >> 2;              // 0..7
    int qc = (lane & 3) * 2;
    #pragma unroll
    for (int nt = 0; nt < 8; ++nt) {
        int col = bn + warp_n * 64 + nt * 8 + qc;
        float2 bv = *(const float2*)(g_bias + col);
        float bx = w2 * bv.x, by = w2 * bv.y;
        #pragma unroll
        for (int mt = 0; mt < 2; ++mt) {
            int row0 = bm + warp_m * 32 + mt * 16 + qr;
            float2 v0 = make_float2(fmaf(w1, acc[mt][nt][0], bx),
                                    fmaf(w1, acc[mt][nt][1], by));
            float2 v1 = make_float2(fmaf(w1, acc[mt][nt][2], bx),
                                    fmaf(w1, acc[mt][nt][3], by));
            *(float2*)(E + (size_t)row0 * L + col)       = v0;
            *(float2*)(E + (size_t)(row0 + 8) * L + col) = v1;
        }
    }
}

// ---------------------------------------------------------------------------
// Kernel E: in-place row softmax over the user-energy slab.
// ---------------------------------------------------------------------------
__global__ void row_softmax_kernel(float* __restrict__ E, int L) {
    __shared__ float sE[L_MAX];
    __shared__ float red[32];
    int tid = threadIdx.x;
    float* row = E + (size_t)blockIdx.x * L;

    float lmax = -INFINITY;
    for (int l = tid; l < L; l += blockDim.x) {
        float v = row[l];
        sE[l] = v;
        lmax = fmaxf(lmax, v);
    }
    float mx = block_reduce(lmax, true, red);

    float lsum = 0.f;
    for (int l = tid; l < L; l += blockDim.x) {
        float v = __expf(sE[l] - mx);
        sE[l] = v;
        lsum += v;
    }
    float inv = 1.0f / block_reduce(lsum, false, red);

    for (int l = tid; l < L; l += blockDim.x)
        row[l] = sE[l] * inv;
}

// ---------------------------------------------------------------------------
// launch (5 graph nodes)
// ---------------------------------------------------------------------------
extern "C" void kernel_launch(void* const* d_in, const int* in_sizes, int n_in,
                              void* d_out, int out_size) {
    const int*   his   = (const int*)d_in[0];
    const int*   cur   = (const int*)d_in[1];
    const int*   his_t = (const int*)d_in[2];
    const int*   cur_t = (const int*)d_in[3];
    const float* poi   = (const float*)d_in[4];
    const float* tsim  = (const float*)d_in[5];
    const float* uemb  = (const float*)d_in[6];
    const float* iemb  = (const float*)d_in[7];
    const float* soc   = (const float*)d_in[8];
    const float* w1    = (const float*)d_in[9];
    const float* w2    = (const float*)d_in[10];

    int L = in_sizes[0];
    int S = in_sizes[1];
    int D = in_sizes[8];
    int NPOI = (int)(sqrt((double)in_sizes[4]) + 0.5);
    int NT   = (int)(sqrt((double)in_sizes[5]) + 0.5);

    float* out      = (float*)d_out;
    float* out_loc  = out;
    float* out_time = out + (size_t)S * L;
    float* out_user = out + 2 * (size_t)S * L;

    cudaFuncSetAttribute(gemm_mma_kernel,
                         cudaFuncAttributeMaxDynamicSharedMemorySize, GEMM_SMEM);

    // prep: L/8 bias blocks + 1 time-table block
    prep_kernel<<<L / 8 + 1, 256>>>(his_t, L, tsim, NT, iemb, soc, D);

    // fused vectorized hi/lo split for A and B
    int chunks = (S + L) * (KP / 8);
    split_bf16_kernel<<<(chunks + 255) / 256, 256>>>(uemb, iemb, D);

    row_loc_time_kernel<<<S, 256>>>(his, cur, his_t, cur_t, poi, NPOI,
                                    out_loc, out_time, L);

    dim3 grid(L / GBN, S / GBM);
    gemm_mma_kernel<<<grid, 256, GEMM_SMEM>>>(w1, w2, out_user, L);

    row_softmax_kernel<<<S, 256>>>(out_user, L);
}